// round 11
// baseline (speedup 1.0000x reference)
#include <cuda_runtime.h>
#include <cstdint>

#define BB   8
#define SQ   2048
#define SKV  1024
#define EMB_ 1024
#define PROJ_ 1024

#define SPAD 20
#define NST  3
#define STAGE_W (128 * SPAD)            // words per tile stage
#define STAGE_B (STAGE_W * 4)           // 10240 bytes
#define SMEM_SZ (NST * STAGE_B * 2)     // 61440 bytes -> 3 CTAs/SM

// ---------------- scratch (allocation-free) ----------------
__device__ float g_q  [(size_t)BB * SQ  * PROJ_];   // 64 MB
__device__ float g_sk [(size_t)BB * SKV * PROJ_];
__device__ float g_vt [(size_t)BB * SKV * PROJ_];   // V^T (subject): [b][p][kv]
__device__ float g_ek [(size_t)BB * SKV * PROJ_];
__device__ float g_evt[(size_t)BB * SKV * PROJ_];   // V^T (scene)
__device__ float g_s1 [(size_t)BB * SQ  * SKV ];    // exp-scores attn1
__device__ float g_s2 [(size_t)BB * SQ  * SKV ];    // exp-scores attn2
// tf32-rounded copies of GEMM inputs
__device__ float g_or [(size_t)BB * SQ  * EMB_];
__device__ float g_sr [(size_t)BB * SKV * EMB_];
__device__ float g_cr [(size_t)BB * SKV * EMB_];
__device__ float g_w  [5][(size_t)PROJ_ * EMB_];

__device__ __forceinline__ uint32_t f2tf32(float x) {
    uint32_t r;
    asm("cvt.rna.tf32.f32 %0, %1;" : "=r"(r) : "f"(x));
    return r;
}
__device__ __forceinline__ uint32_t smem_u32(const void* p) {
    uint32_t a;
    asm("{ .reg .u64 t; cvta.to.shared.u64 t, %1; cvt.u32.u64 %0, t; }" : "=r"(a) : "l"(p));
    return a;
}

#define CPA(dst, src) asm volatile("cp.async.cg.shared.global [%0], [%1], 16;" :: "r"(dst), "l"(src))
#define CPC()         asm volatile("cp.async.commit_group;" ::: "memory")
#define CPW(n)        asm volatile("cp.async.wait_group %0;" :: "n"(n) : "memory")
#define LDSM4(r0,r1,r2,r3,a) asm volatile("ldmatrix.sync.aligned.m8n8.x4.shared.b16 {%0,%1,%2,%3}, [%4];" \
    : "=r"(r0),"=r"(r1),"=r"(r2),"=r"(r3) : "r"(a))

// ---------------- pre-round inputs to tf32 ----------------
__global__ void round_kernel(const float* __restrict__ in, float* __restrict__ out, int n4)
{
    int i = blockIdx.x * blockDim.x + threadIdx.x;
    if (i >= n4) return;
    float4 v = ((const float4*)in)[i];
    uint4 u = make_uint4(f2tf32(v.x), f2tf32(v.y), f2tf32(v.z), f2tf32(v.w));
    ((uint4*)out)[i] = u;
}

// ---------------- tf32 mma.sync NT GEMM ----------------
// C[m,n] = alpha * sum_k A[m,k]*B[n,k] (+bias[n]).  A:[M,K], B:[N,K] row-major,
// values already tf32-rounded. CTA 128x128, 4 warps, warp tile 64x64, k-chunk 16,
// 3-stage cp.async pipeline, ldmatrix x4 loads.
// TRANS_OUT: write C^T per 1024-row batch.
// EXPOUT:    C = exp(alpha*acc)  (fused softmax numerator; scores are small -> no max needed)
// NORM:      C = acc / rowsum(A) (fused softmax denominator: rowsum accumulated from A frags)
// cvt_out:   round outputs to tf32 for chaining.
template <bool TRANS_OUT, bool EXPOUT, bool NORM>
__global__ void __launch_bounds__(128, 3) mma_gemm(
    const float* __restrict__ A, const float* __restrict__ B,
    const float* __restrict__ bias, float* __restrict__ C,
    int K, int lda, int ldb, int ldc, float alpha, int cvt_out,
    long long sA, long long sB, long long sC)
{
    extern __shared__ __align__(16) uint32_t sm[];
    const uint32_t sA_base = smem_u32(sm);
    const uint32_t sB_base = sA_base + NST * STAGE_B;

    A += (long long)blockIdx.z * sA;
    B += (long long)blockIdx.z * sB;
    C += (long long)blockIdx.z * sC;
    const int m0 = blockIdx.y * 128;
    const int n0 = blockIdx.x * 128;

    const int tid  = threadIdx.x;
    const int lane = tid & 31;
    const int wid  = tid >> 5;          // 0..3
    const int wm   = wid >> 1;          // warp m offset = wm*64
    const int wn   = wid & 1;           // warp n offset = wn*64
    const int g    = lane >> 2;
    const int tg   = lane & 3;

    // ldmatrix lane-address offsets (bytes)
    const int r8   = lane & 7;
    const int sel  = lane >> 3;                 // 0..3
    const int sel8 = sel & 1;
    const uint32_t aoff = (uint32_t)(((r8 + (sel8 << 3)) * SPAD + ((sel >> 1) << 2)) << 2);
    const uint32_t boff = (uint32_t)((((lane >> 4) * 8 + r8) * SPAD + (sel8 << 2)) << 2);

    // loader mapping: thread -> (row = tid>>2 + i*32, kq = (tid&3)*4), i = 0..3
    const int lrow = tid >> 2;
    const int lkq  = (tid & 3) << 2;
    const float* Ap = A + (long long)(m0 + lrow) * lda + lkq;
    const float* Bp = B + (long long)(n0 + lrow) * ldb + lkq;
    const uint32_t dA = sA_base + (uint32_t)((lrow * SPAD + lkq) << 2);
    const uint32_t dB = sB_base + (uint32_t)((lrow * SPAD + lkq) << 2);
    const long long a32 = 32ll * lda, b32 = 32ll * ldb;

    float acc[4][8][4];
#pragma unroll
    for (int i = 0; i < 4; i++)
#pragma unroll
        for (int j = 0; j < 8; j++)
#pragma unroll
            for (int c = 0; c < 4; c++) acc[i][j][c] = 0.0f;

    float rs0[4], rs1[4];               // rowsum accumulators (NORM)
#pragma unroll
    for (int i = 0; i < 4; i++) { rs0[i] = 0.0f; rs1[i] = 0.0f; }

    const int niter = K >> 4;

    // prologue: issue stages 0..NST-2
#pragma unroll
    for (int s = 0; s < NST - 1; s++) {
        const float* Aps = Ap + (s << 4);
        const float* Bps = Bp + (s << 4);
        const uint32_t da = dA + s * STAGE_B;
        const uint32_t db = dB + s * STAGE_B;
#pragma unroll
        for (int i = 0; i < 4; i++) CPA(da + i * (32 * SPAD * 4), Aps + i * a32);
#pragma unroll
        for (int i = 0; i < 4; i++) CPA(db + i * (32 * SPAD * 4), Bps + i * b32);
        CPC();
    }

    for (int it = 0; it < niter; it++) {
        const int cur = it % NST;
        CPW(NST - 2);
        __syncthreads();

        const int nit = it + NST - 1;
        if (nit < niter) {
            const int s = nit % NST;
            const float* Aps = Ap + (nit << 4);
            const float* Bps = Bp + (nit << 4);
            const uint32_t da = dA + s * STAGE_B;
            const uint32_t db = dB + s * STAGE_B;
#pragma unroll
            for (int i = 0; i < 4; i++) CPA(da + i * (32 * SPAD * 4), Aps + i * a32);
#pragma unroll
            for (int i = 0; i < 4; i++) CPA(db + i * (32 * SPAD * 4), Bps + i * b32);
            CPC();
        }

        const uint32_t sa = sA_base + cur * STAGE_B;
        const uint32_t sb = sB_base + cur * STAGE_B;
#pragma unroll
        for (int ksi = 0; ksi < 2; ksi++) {
            const int ks = ksi << 3;
            uint32_t af[4][4];
#pragma unroll
            for (int mt = 0; mt < 4; mt++) {
                uint32_t ad = sa + (uint32_t)((((wm * 64 + mt * 16) * SPAD + ks) << 2)) + aoff;
                LDSM4(af[mt][0], af[mt][1], af[mt][2], af[mt][3], ad);
            }
            if (NORM) {
                // a0=row g,col tg ; a1=row g+8,col tg ; a2=row g,col tg+4 ; a3=row g+8,col tg+4
#pragma unroll
                for (int mt = 0; mt < 4; mt++) {
                    rs0[mt] += __uint_as_float(af[mt][0]) + __uint_as_float(af[mt][2]);
                    rs1[mt] += __uint_as_float(af[mt][1]) + __uint_as_float(af[mt][3]);
                }
            }
            uint32_t bf[8][2];
#pragma unroll
            for (int j = 0; j < 4; j++) {
                uint32_t bd = sb + (uint32_t)((((wn * 64 + j * 16) * SPAD + ks) << 2)) + boff;
                LDSM4(bf[2 * j][0], bf[2 * j][1], bf[2 * j + 1][0], bf[2 * j + 1][1], bd);
            }
#pragma unroll
            for (int mt = 0; mt < 4; mt++)
#pragma unroll
                for (int nt = 0; nt < 8; nt++) {
                    asm volatile(
                        "mma.sync.aligned.m16n8k8.row.col.f32.tf32.tf32.f32 "
                        "{%0,%1,%2,%3}, {%4,%5,%6,%7}, {%8,%9}, {%0,%1,%2,%3};"
                        : "+f"(acc[mt][nt][0]), "+f"(acc[mt][nt][1]),
                          "+f"(acc[mt][nt][2]), "+f"(acc[mt][nt][3])
                        : "r"(af[mt][0]), "r"(af[mt][1]), "r"(af[mt][2]), "r"(af[mt][3]),
                          "r"(bf[nt][0]), "r"(bf[nt][1]));
                }
        }
    }

    // ---------------- epilogue ----------------
#pragma unroll
    for (int mt = 0; mt < 4; mt++) {
        int m = m0 + wm * 64 + mt * 16 + g;
        float inv0 = 1.0f, inv1 = 1.0f;
        if (NORM) {
            float s0 = rs0[mt], s1 = rs1[mt];
            s0 += __shfl_xor_sync(0xffffffffu, s0, 1);
            s0 += __shfl_xor_sync(0xffffffffu, s0, 2);
            s1 += __shfl_xor_sync(0xffffffffu, s1, 1);
            s1 += __shfl_xor_sync(0xffffffffu, s1, 2);
            inv0 = 1.0f / s0;
            inv1 = 1.0f / s1;
        }
#pragma unroll
        for (int nt = 0; nt < 8; nt++) {
            int n = n0 + wn * 64 + nt * 8 + 2 * tg;
            float bx = 0.f, by = 0.f;
            if (bias) { bx = __ldg(bias + n); by = __ldg(bias + n + 1); }
            float v0 = acc[mt][nt][0] * alpha + bx;
            float v1 = acc[mt][nt][1] * alpha + by;
            float v2 = acc[mt][nt][2] * alpha + bx;
            float v3 = acc[mt][nt][3] * alpha + by;
            if (EXPOUT) {
                v0 = __expf(v0); v1 = __expf(v1);
                v2 = __expf(v2); v3 = __expf(v3);
            }
            if (NORM) {
                v0 *= inv0; v1 *= inv0;
                v2 *= inv1; v3 *= inv1;
            }
            if (cvt_out) {
                v0 = __uint_as_float(f2tf32(v0));
                v1 = __uint_as_float(f2tf32(v1));
                v2 = __uint_as_float(f2tf32(v2));
                v3 = __uint_as_float(f2tf32(v3));
            }
            if (TRANS_OUT) {
                long long base0 = (long long)(m >> 10) * (1024ll * 1024) + (m & 1023);
                long long base1 = (long long)((m + 8) >> 10) * (1024ll * 1024) + ((m + 8) & 1023);
                C[base0 + (long long)n * 1024]       = v0;
                C[base0 + (long long)(n + 1) * 1024] = v1;
                C[base1 + (long long)n * 1024]       = v2;
                C[base1 + (long long)(n + 1) * 1024] = v3;
            } else {
                *(float2*)(C + (long long)m * ldc + n)       = make_float2(v0, v1);
                *(float2*)(C + (long long)(m + 8) * ldc + n) = make_float2(v2, v3);
            }
        }
    }
}

// ---------------- reductions ----------------
__device__ __forceinline__ float block_sum256(float v, float* red) {
#pragma unroll
    for (int o = 16; o; o >>= 1) v += __shfl_xor_sync(0xffffffffu, v, o);
    if ((threadIdx.x & 31) == 0) red[threadIdx.x >> 5] = v;
    __syncthreads();
    float r = red[0];
#pragma unroll
    for (int i = 1; i < 8; i++) r += red[i];
    __syncthreads();
    return r;
}

// ---------------- residual + layernorm (in place) ----------------
__global__ void ln_kernel(const float* __restrict__ obj, float* __restrict__ io,
                          const float* __restrict__ gamma, const float* __restrict__ beta)
{
    __shared__ float red[8];
    const size_t row = blockIdx.x;
    const float4* o4 = (const float4*)(obj + row * EMB_);
    float4*       y4 = (float4*)(io + row * EMB_);
    const int t = threadIdx.x;
    float4 a = o4[t], b = y4[t];
    float4 x = make_float4(a.x + b.x, a.y + b.y, a.z + b.z, a.w + b.w);
    float s = x.x + x.y + x.z + x.w;
    s = block_sum256(s, red);
    const float mu = s * (1.0f / EMB_);
    float dx = x.x - mu, dy = x.y - mu, dz = x.z - mu, dw = x.w - mu;
    float vs = dx * dx + dy * dy + dz * dz + dw * dw;
    vs = block_sum256(vs, red);
    const float rs = rsqrtf(vs * (1.0f / EMB_) + 1e-5f);
    float4 gm = ((const float4*)gamma)[t];
    float4 be = ((const float4*)beta)[t];
    float4 y;
    y.x = dx * rs * gm.x + be.x;
    y.y = dy * rs * gm.y + be.y;
    y.z = dz * rs * gm.z + be.z;
    y.w = dw * rs * gm.w + be.w;
    y4[t] = y;
}

// ---------------- launch ----------------
extern "C" void kernel_launch(void* const* d_in, const int* in_sizes, int n_in,
                              void* d_out, int out_size)
{
    const float* obj   = (const float*)d_in[0];
    const float* sub   = (const float*)d_in[1];
    const float* scene = (const float*)d_in[2];
    const float* W_q  = (const float*)d_in[3];  const float* b_q  = (const float*)d_in[4];
    const float* W_sk = (const float*)d_in[5];  const float* b_sk = (const float*)d_in[6];
    const float* W_sv = (const float*)d_in[7];  const float* b_sv = (const float*)d_in[8];
    const float* W_ek = (const float*)d_in[9];  const float* b_ek = (const float*)d_in[10];
    const float* W_ev = (const float*)d_in[11]; const float* b_ev = (const float*)d_in[12];
    const float* ln_g = (const float*)d_in[13]; const float* ln_b = (const float*)d_in[14];

    float* out = (float*)d_out;
    float* O1 = out;
    float* O2 = out + (size_t)BB * SQ * PROJ_;

    float *q, *sk, *vt, *ek, *evt, *S1, *S2, *orr, *srr, *crr, *wr;
    cudaGetSymbolAddress((void**)&q,   g_q);
    cudaGetSymbolAddress((void**)&sk,  g_sk);
    cudaGetSymbolAddress((void**)&vt,  g_vt);
    cudaGetSymbolAddress((void**)&ek,  g_ek);
    cudaGetSymbolAddress((void**)&evt, g_evt);
    cudaGetSymbolAddress((void**)&S1,  g_s1);
    cudaGetSymbolAddress((void**)&S2,  g_s2);
    cudaGetSymbolAddress((void**)&orr, g_or);
    cudaGetSymbolAddress((void**)&srr, g_sr);
    cudaGetSymbolAddress((void**)&crr, g_cr);
    cudaGetSymbolAddress((void**)&wr,  g_w);

    cudaFuncSetAttribute(mma_gemm<false, false, false>, cudaFuncAttributeMaxDynamicSharedMemorySize, SMEM_SZ);
    cudaFuncSetAttribute(mma_gemm<true,  false, false>, cudaFuncAttributeMaxDynamicSharedMemorySize, SMEM_SZ);
    cudaFuncSetAttribute(mma_gemm<false, true,  false>, cudaFuncAttributeMaxDynamicSharedMemorySize, SMEM_SZ);
    cudaFuncSetAttribute(mma_gemm<false, false, true >, cudaFuncAttributeMaxDynamicSharedMemorySize, SMEM_SZ);

    // streams/events created once (host resources; per-call GPU work is identical)
    static cudaStream_t st1 = nullptr, st2 = nullptr;
    static cudaEvent_t eFork = nullptr, eQ = nullptr, eS = nullptr, eJoin = nullptr;
    if (!st1) {
        cudaStreamCreateWithFlags(&st1, cudaStreamNonBlocking);
        cudaStreamCreateWithFlags(&st2, cudaStreamNonBlocking);
        cudaEventCreateWithFlags(&eFork, cudaEventDisableTiming);
        cudaEventCreateWithFlags(&eQ,    cudaEventDisableTiming);
        cudaEventCreateWithFlags(&eS,    cudaEventDisableTiming);
        cudaEventCreateWithFlags(&eJoin, cudaEventDisableTiming);
    }

    const dim3 blk(128);
    const float scale = 0.03125f;  // 1024^-0.5
    const long long ZP = (long long)SQ * PROJ_;
    const long long ZS = (long long)SQ * SKV;
    const long long ZV = (long long)SKV * PROJ_;
    const size_t WSZ = (size_t)PROJ_ * EMB_;
    const int NB4 = BB * SKV * EMB_ / 4;
    const int NW4 = (int)(WSZ / 4);

    // ---- fork
    cudaEventRecord(eFork, 0);
    cudaStreamWaitEvent(st1, eFork, 0);
    cudaStreamWaitEvent(st2, eFork, 0);

    // ---- stream 0: obj round -> Q proj -> (record eQ)
    round_kernel<<<(BB * SQ * EMB_ / 4 + 255) / 256, 256>>>(obj, orr, BB * SQ * EMB_ / 4);
    round_kernel<<<(NW4 + 255) / 256, 256>>>(W_q, wr + 0 * WSZ, NW4);
    mma_gemm<false, false, false><<<dim3(8, 128, 1), blk, SMEM_SZ>>>(orr, wr + 0 * WSZ, b_q, q, EMB_, EMB_, EMB_, PROJ_, 1.0f, 1, 0, 0, 0);
    cudaEventRecord(eQ, 0);

    // ---- stream 1: sub rounds -> sk proj, vt proj -> (record eS)
    round_kernel<<<(NB4 + 255) / 256, 256, 0, st1>>>(sub, srr, NB4);
    round_kernel<<<(NW4 + 255) / 256, 256, 0, st1>>>(W_sk, wr + 1 * WSZ, NW4);
    round_kernel<<<(NW4 + 255) / 256, 256, 0, st1>>>(W_sv, wr + 2 * WSZ, NW4);
    mma_gemm<false, false, false><<<dim3(8, 64, 1), blk, SMEM_SZ, st1>>>(srr, wr + 1 * WSZ, b_sk, sk, EMB_, EMB_, EMB_, PROJ_, 1.0f, 1, 0, 0, 0);
    mma_gemm<true,  false, false><<<dim3(8, 64, 1), blk, SMEM_SZ, st1>>>(srr, wr + 2 * WSZ, b_sv, vt, EMB_, EMB_, EMB_, PROJ_, 1.0f, 1, 0, 0, 0);
    cudaEventRecord(eS, st1);

    // ---- stream 2: scene rounds -> ek proj, evt proj -> wait eQ -> attn2 chain
    round_kernel<<<(NB4 + 255) / 256, 256, 0, st2>>>(scene, crr, NB4);
    round_kernel<<<(NW4 + 255) / 256, 256, 0, st2>>>(W_ek, wr + 3 * WSZ, NW4);
    round_kernel<<<(NW4 + 255) / 256, 256, 0, st2>>>(W_ev, wr + 4 * WSZ, NW4);
    mma_gemm<false, false, false><<<dim3(8, 64, 1), blk, SMEM_SZ, st2>>>(crr, wr + 3 * WSZ, b_ek, ek, EMB_, EMB_, EMB_, PROJ_, 1.0f, 1, 0, 0, 0);
    mma_gemm<true,  false, false><<<dim3(8, 64, 1), blk, SMEM_SZ, st2>>>(crr, wr + 4 * WSZ, b_ev, evt, EMB_, EMB_, EMB_, PROJ_, 1.0f, 1, 0, 0, 0);
    cudaStreamWaitEvent(st2, eQ, 0);
    // E2 = exp(scale * q ek^T), rounded to tf32
    mma_gemm<false, true, false><<<dim3(8, 16, BB), blk, SMEM_SZ, st2>>>(q, ek, nullptr, S2, PROJ_, PROJ_, PROJ_, SKV, scale, 1, ZP, ZV, ZS);
    // O2 = (E2 V2) / rowsum(E2)
    mma_gemm<false, false, true><<<dim3(8, 16, BB), blk, SMEM_SZ, st2>>>(S2, evt, nullptr, O2, SKV, SKV, SKV, PROJ_, 1.0f, 0, ZS, ZV, ZP);
    ln_kernel<<<BB * SQ, dim3(256), 0, st2>>>(obj, O2, ln_g, ln_b);
    cudaEventRecord(eJoin, st2);

    // ---- stream 0: wait sub projections -> attn1 chain
    cudaStreamWaitEvent(0, eS, 0);
    mma_gemm<false, true, false><<<dim3(8, 16, BB), blk, SMEM_SZ>>>(q, sk, nullptr, S1, PROJ_, PROJ_, PROJ_, SKV, scale, 1, ZP, ZV, ZS);
    mma_gemm<false, false, true><<<dim3(8, 16, BB), blk, SMEM_SZ>>>(S1, vt, nullptr, O1, SKV, SKV, SKV, PROJ_, 1.0f, 0, ZS, ZV, ZP);
    ln_kernel<<<BB * SQ, dim3(256)>>>(obj, O1, ln_g, ln_b);

    // ---- join attn2 back into stream 0
    cudaStreamWaitEvent(0, eJoin, 0);
}

// round 12
// speedup vs baseline: 1.1271x; 1.1271x over previous
#include <cuda_runtime.h>
#include <cstdint>

#define BB   8
#define SQ   2048
#define SKV  1024
#define EMB_ 1024
#define PROJ_ 1024

#define SPAD 20
#define NST  3
#define STAGE_W (128 * SPAD)            // words per tile stage
#define STAGE_B (STAGE_W * 4)           // 10240 bytes
#define SMEM_SZ (NST * STAGE_B * 2)     // 61440 bytes

// ---------------- scratch (allocation-free) ----------------
__device__ float g_q  [(size_t)BB * SQ  * PROJ_];   // 64 MB
__device__ float g_sk [(size_t)BB * SKV * PROJ_];
__device__ float g_vt [(size_t)BB * SKV * PROJ_];   // V^T (subject): [b][p][kv]
__device__ float g_ek [(size_t)BB * SKV * PROJ_];
__device__ float g_evt[(size_t)BB * SKV * PROJ_];   // V^T (scene)
__device__ float g_s1 [(size_t)BB * SQ  * SKV ];    // scores attn1
__device__ float g_s2 [(size_t)BB * SQ  * SKV ];    // scores attn2
// tf32-rounded copies of GEMM inputs
__device__ float g_or [(size_t)BB * SQ  * EMB_];
__device__ float g_sr [(size_t)BB * SKV * EMB_];
__device__ float g_cr [(size_t)BB * SKV * EMB_];
__device__ float g_w  [5][(size_t)PROJ_ * EMB_];

__device__ __forceinline__ uint32_t f2tf32(float x) {
    uint32_t r;
    asm("cvt.rna.tf32.f32 %0, %1;" : "=r"(r) : "f"(x));
    return r;
}
__device__ __forceinline__ uint32_t smem_u32(const void* p) {
    uint32_t a;
    asm("{ .reg .u64 t; cvta.to.shared.u64 t, %1; cvt.u32.u64 %0, t; }" : "=r"(a) : "l"(p));
    return a;
}

#define CPA(dst, src) asm volatile("cp.async.cg.shared.global [%0], [%1], 16;" :: "r"(dst), "l"(src))
#define CPC()         asm volatile("cp.async.commit_group;" ::: "memory")
#define CPW(n)        asm volatile("cp.async.wait_group %0;" :: "n"(n) : "memory")
#define LDSM4(r0,r1,r2,r3,a) asm volatile("ldmatrix.sync.aligned.m8n8.x4.shared.b16 {%0,%1,%2,%3}, [%4];" \
    : "=r"(r0),"=r"(r1),"=r"(r2),"=r"(r3) : "r"(a))

// ---------------- pre-round inputs to tf32 ----------------
__global__ void round_kernel(const float* __restrict__ in, float* __restrict__ out, int n4)
{
    int i = blockIdx.x * blockDim.x + threadIdx.x;
    if (i >= n4) return;
    float4 v = ((const float4*)in)[i];
    uint4 u = make_uint4(f2tf32(v.x), f2tf32(v.y), f2tf32(v.z), f2tf32(v.w));
    ((uint4*)out)[i] = u;
}

// ---------------- tf32 mma.sync NT GEMM ----------------
// C[m,n] = alpha * sum_k A[m,k]*B[n,k] (+bias[n]).  A:[M,K], B:[N,K] row-major,
// values already tf32-rounded. CTA 128x128, 4 warps, warp tile 64x64, k-chunk 16,
// 3-stage cp.async pipeline (1 group in flight across barrier), ldmatrix x4 loads.
// TRANS_OUT: write C^T per 1024-row batch.  cvt_out: round outputs to tf32.
template <bool TRANS_OUT>
__global__ void __launch_bounds__(128, 2) mma_gemm(
    const float* __restrict__ A, const float* __restrict__ B,
    const float* __restrict__ bias, float* __restrict__ C,
    int K, int lda, int ldb, int ldc, float alpha, int cvt_out,
    long long sA, long long sB, long long sC)
{
    extern __shared__ __align__(16) uint32_t sm[];
    const uint32_t sA_base = smem_u32(sm);
    const uint32_t sB_base = sA_base + NST * STAGE_B;

    A += (long long)blockIdx.z * sA;
    B += (long long)blockIdx.z * sB;
    C += (long long)blockIdx.z * sC;
    const int m0 = blockIdx.y * 128;
    const int n0 = blockIdx.x * 128;

    const int tid  = threadIdx.x;
    const int lane = tid & 31;
    const int wid  = tid >> 5;          // 0..3
    const int wm   = wid >> 1;          // warp m offset = wm*64
    const int wn   = wid & 1;           // warp n offset = wn*64
    const int g    = lane >> 2;
    const int tg   = lane & 3;

    // ldmatrix lane-address offsets (bytes)
    const int r8   = lane & 7;
    const int sel  = lane >> 3;                 // 0..3
    const int sel8 = sel & 1;
    // A x4: m0=rows r8 col0, m1=rows r8+8 col0, m2=rows r8 col4, m3=rows r8+8 col4
    const uint32_t aoff = (uint32_t)(((r8 + (sel8 << 3)) * SPAD + ((sel >> 1) << 2)) << 2);
    // B x4 (two nt tiles): lanes 0-15 -> tile j rows r8, cols 0/4; lanes 16-31 -> tile j+1
    const uint32_t boff = (uint32_t)((((lane >> 4) * 8 + r8) * SPAD + (sel8 << 2)) << 2);

    // loader mapping: thread -> (row = tid>>2 + i*32, kq = (tid&3)*4), i = 0..3
    const int lrow = tid >> 2;
    const int lkq  = (tid & 3) << 2;
    const float* Ap = A + (long long)(m0 + lrow) * lda + lkq;
    const float* Bp = B + (long long)(n0 + lrow) * ldb + lkq;
    const uint32_t dA = sA_base + (uint32_t)((lrow * SPAD + lkq) << 2);
    const uint32_t dB = sB_base + (uint32_t)((lrow * SPAD + lkq) << 2);
    const long long a32 = 32ll * lda, b32 = 32ll * ldb;

    float acc[4][8][4];
#pragma unroll
    for (int i = 0; i < 4; i++)
#pragma unroll
        for (int j = 0; j < 8; j++)
#pragma unroll
            for (int c = 0; c < 4; c++) acc[i][j][c] = 0.0f;

    const int niter = K >> 4;

    // prologue: issue stages 0..NST-2
#pragma unroll
    for (int s = 0; s < NST - 1; s++) {
        const float* Aps = Ap + (s << 4);
        const float* Bps = Bp + (s << 4);
        const uint32_t da = dA + s * STAGE_B;
        const uint32_t db = dB + s * STAGE_B;
#pragma unroll
        for (int i = 0; i < 4; i++) CPA(da + i * (32 * SPAD * 4), Aps + i * a32);
#pragma unroll
        for (int i = 0; i < 4; i++) CPA(db + i * (32 * SPAD * 4), Bps + i * b32);
        CPC();
    }

    for (int it = 0; it < niter; it++) {
        const int cur = it % NST;
        CPW(NST - 2);
        __syncthreads();

        const int nit = it + NST - 1;
        if (nit < niter) {
            const int s = nit % NST;
            const float* Aps = Ap + (nit << 4);
            const float* Bps = Bp + (nit << 4);
            const uint32_t da = dA + s * STAGE_B;
            const uint32_t db = dB + s * STAGE_B;
#pragma unroll
            for (int i = 0; i < 4; i++) CPA(da + i * (32 * SPAD * 4), Aps + i * a32);
#pragma unroll
            for (int i = 0; i < 4; i++) CPA(db + i * (32 * SPAD * 4), Bps + i * b32);
            CPC();
        }

        const uint32_t sa = sA_base + cur * STAGE_B;
        const uint32_t sb = sB_base + cur * STAGE_B;
#pragma unroll
        for (int ksi = 0; ksi < 2; ksi++) {
            const int ks = ksi << 3;
            uint32_t af[4][4];
#pragma unroll
            for (int mt = 0; mt < 4; mt++) {
                uint32_t ad = sa + (uint32_t)((((wm * 64 + mt * 16) * SPAD + ks) << 2)) + aoff;
                LDSM4(af[mt][0], af[mt][1], af[mt][2], af[mt][3], ad);
            }
            uint32_t bf[8][2];
#pragma unroll
            for (int j = 0; j < 4; j++) {
                uint32_t bd = sb + (uint32_t)((((wn * 64 + j * 16) * SPAD + ks) << 2)) + boff;
                LDSM4(bf[2 * j][0], bf[2 * j][1], bf[2 * j + 1][0], bf[2 * j + 1][1], bd);
            }
#pragma unroll
            for (int mt = 0; mt < 4; mt++)
#pragma unroll
                for (int nt = 0; nt < 8; nt++) {
                    asm volatile(
                        "mma.sync.aligned.m16n8k8.row.col.f32.tf32.tf32.f32 "
                        "{%0,%1,%2,%3}, {%4,%5,%6,%7}, {%8,%9}, {%0,%1,%2,%3};"
                        : "+f"(acc[mt][nt][0]), "+f"(acc[mt][nt][1]),
                          "+f"(acc[mt][nt][2]), "+f"(acc[mt][nt][3])
                        : "r"(af[mt][0]), "r"(af[mt][1]), "r"(af[mt][2]), "r"(af[mt][3]),
                          "r"(bf[nt][0]), "r"(bf[nt][1]));
                }
        }
    }

    // ---------------- epilogue ----------------
#pragma unroll
    for (int mt = 0; mt < 4; mt++) {
        int m = m0 + wm * 64 + mt * 16 + g;
#pragma unroll
        for (int nt = 0; nt < 8; nt++) {
            int n = n0 + wn * 64 + nt * 8 + 2 * tg;
            float bx = 0.f, by = 0.f;
            if (bias) { bx = __ldg(bias + n); by = __ldg(bias + n + 1); }
            float v0 = acc[mt][nt][0] * alpha + bx;
            float v1 = acc[mt][nt][1] * alpha + by;
            float v2 = acc[mt][nt][2] * alpha + bx;
            float v3 = acc[mt][nt][3] * alpha + by;
            if (cvt_out) {
                v0 = __uint_as_float(f2tf32(v0));
                v1 = __uint_as_float(f2tf32(v1));
                v2 = __uint_as_float(f2tf32(v2));
                v3 = __uint_as_float(f2tf32(v3));
            }
            if (TRANS_OUT) {
                long long base0 = (long long)(m >> 10) * (1024ll * 1024) + (m & 1023);
                long long base1 = (long long)((m + 8) >> 10) * (1024ll * 1024) + ((m + 8) & 1023);
                C[base0 + (long long)n * 1024]       = v0;
                C[base0 + (long long)(n + 1) * 1024] = v1;
                C[base1 + (long long)n * 1024]       = v2;
                C[base1 + (long long)(n + 1) * 1024] = v3;
            } else {
                *(float2*)(C + (long long)m * ldc + n)       = make_float2(v0, v1);
                *(float2*)(C + (long long)(m + 8) * ldc + n) = make_float2(v2, v3);
            }
        }
    }
}

// ---------------- reductions ----------------
__device__ __forceinline__ float block_sum256(float v, float* red) {
#pragma unroll
    for (int o = 16; o; o >>= 1) v += __shfl_xor_sync(0xffffffffu, v, o);
    if ((threadIdx.x & 31) == 0) red[threadIdx.x >> 5] = v;
    __syncthreads();
    float r = red[0];
#pragma unroll
    for (int i = 1; i < 8; i++) r += red[i];
    __syncthreads();
    return r;
}
__device__ __forceinline__ float block_max256(float v, float* red) {
#pragma unroll
    for (int o = 16; o; o >>= 1) v = fmaxf(v, __shfl_xor_sync(0xffffffffu, v, o));
    if ((threadIdx.x & 31) == 0) red[threadIdx.x >> 5] = v;
    __syncthreads();
    float r = red[0];
#pragma unroll
    for (int i = 1; i < 8; i++) r = fmaxf(r, red[i]);
    __syncthreads();
    return r;
}

// ---------------- softmax over rows of length 1024 (stores tf32-rounded) ----------------
__global__ void softmax_kernel(float* __restrict__ S)
{
    __shared__ float red[8];
    float* row = S + (size_t)blockIdx.x * SKV;
    const int t = threadIdx.x;
    float4 v = ((const float4*)row)[t];
    float m = fmaxf(fmaxf(v.x, v.y), fmaxf(v.z, v.w));
    m = block_max256(m, red);
    v.x = __expf(v.x - m); v.y = __expf(v.y - m);
    v.z = __expf(v.z - m); v.w = __expf(v.w - m);
    float s = v.x + v.y + v.z + v.w;
    s = block_sum256(s, red);
    float inv = 1.0f / s;
    uint4 u = make_uint4(f2tf32(v.x * inv), f2tf32(v.y * inv),
                         f2tf32(v.z * inv), f2tf32(v.w * inv));
    ((uint4*)row)[t] = u;
}

// ---------------- residual + layernorm (in place) ----------------
__global__ void ln_kernel(const float* __restrict__ obj, float* __restrict__ io,
                          const float* __restrict__ gamma, const float* __restrict__ beta)
{
    __shared__ float red[8];
    const size_t row = blockIdx.x;
    const float4* o4 = (const float4*)(obj + row * EMB_);
    float4*       y4 = (float4*)(io + row * EMB_);
    const int t = threadIdx.x;
    float4 a = o4[t], b = y4[t];
    float4 x = make_float4(a.x + b.x, a.y + b.y, a.z + b.z, a.w + b.w);
    float s = x.x + x.y + x.z + x.w;
    s = block_sum256(s, red);
    const float mu = s * (1.0f / EMB_);
    float dx = x.x - mu, dy = x.y - mu, dz = x.z - mu, dw = x.w - mu;
    float vs = dx * dx + dy * dy + dz * dz + dw * dw;
    vs = block_sum256(vs, red);
    const float rs = rsqrtf(vs * (1.0f / EMB_) + 1e-5f);
    float4 gm = ((const float4*)gamma)[t];
    float4 be = ((const float4*)beta)[t];
    float4 y;
    y.x = dx * rs * gm.x + be.x;
    y.y = dy * rs * gm.y + be.y;
    y.z = dz * rs * gm.z + be.z;
    y.w = dw * rs * gm.w + be.w;
    y4[t] = y;
}

// ---------------- launch ----------------
extern "C" void kernel_launch(void* const* d_in, const int* in_sizes, int n_in,
                              void* d_out, int out_size)
{
    const float* obj   = (const float*)d_in[0];
    const float* sub   = (const float*)d_in[1];
    const float* scene = (const float*)d_in[2];
    const float* W_q  = (const float*)d_in[3];  const float* b_q  = (const float*)d_in[4];
    const float* W_sk = (const float*)d_in[5];  const float* b_sk = (const float*)d_in[6];
    const float* W_sv = (const float*)d_in[7];  const float* b_sv = (const float*)d_in[8];
    const float* W_ek = (const float*)d_in[9];  const float* b_ek = (const float*)d_in[10];
    const float* W_ev = (const float*)d_in[11]; const float* b_ev = (const float*)d_in[12];
    const float* ln_g = (const float*)d_in[13]; const float* ln_b = (const float*)d_in[14];

    float* out = (float*)d_out;
    float* O1 = out;
    float* O2 = out + (size_t)BB * SQ * PROJ_;

    float *q, *sk, *vt, *ek, *evt, *S1, *S2, *orr, *srr, *crr, *wr;
    cudaGetSymbolAddress((void**)&q,   g_q);
    cudaGetSymbolAddress((void**)&sk,  g_sk);
    cudaGetSymbolAddress((void**)&vt,  g_vt);
    cudaGetSymbolAddress((void**)&ek,  g_ek);
    cudaGetSymbolAddress((void**)&evt, g_evt);
    cudaGetSymbolAddress((void**)&S1,  g_s1);
    cudaGetSymbolAddress((void**)&S2,  g_s2);
    cudaGetSymbolAddress((void**)&orr, g_or);
    cudaGetSymbolAddress((void**)&srr, g_sr);
    cudaGetSymbolAddress((void**)&crr, g_cr);
    cudaGetSymbolAddress((void**)&wr,  g_w);

    cudaFuncSetAttribute(mma_gemm<false>, cudaFuncAttributeMaxDynamicSharedMemorySize, SMEM_SZ);
    cudaFuncSetAttribute(mma_gemm<true>,  cudaFuncAttributeMaxDynamicSharedMemorySize, SMEM_SZ);

    // streams/events created once (host resources; per-call GPU work is identical)
    static cudaStream_t st1 = nullptr, st2 = nullptr;
    static cudaEvent_t eFork = nullptr, eQ = nullptr, eS = nullptr, eJoin = nullptr;
    if (!st1) {
        cudaStreamCreateWithFlags(&st1, cudaStreamNonBlocking);
        cudaStreamCreateWithFlags(&st2, cudaStreamNonBlocking);
        cudaEventCreateWithFlags(&eFork, cudaEventDisableTiming);
        cudaEventCreateWithFlags(&eQ,    cudaEventDisableTiming);
        cudaEventCreateWithFlags(&eS,    cudaEventDisableTiming);
        cudaEventCreateWithFlags(&eJoin, cudaEventDisableTiming);
    }

    const dim3 blk(128);
    const float scale = 0.03125f;  // 1024^-0.5
    const long long ZP = (long long)SQ * PROJ_;
    const long long ZS = (long long)SQ * SKV;
    const long long ZV = (long long)SKV * PROJ_;
    const size_t WSZ = (size_t)PROJ_ * EMB_;
    const int NB4 = BB * SKV * EMB_ / 4;
    const int NW4 = (int)(WSZ / 4);

    // ---- fork
    cudaEventRecord(eFork, 0);
    cudaStreamWaitEvent(st1, eFork, 0);
    cudaStreamWaitEvent(st2, eFork, 0);

    // ---- stream 0: obj round -> Q proj -> (record eQ)
    round_kernel<<<(BB * SQ * EMB_ / 4 + 255) / 256, 256>>>(obj, orr, BB * SQ * EMB_ / 4);
    round_kernel<<<(NW4 + 255) / 256, 256>>>(W_q, wr + 0 * WSZ, NW4);
    mma_gemm<false><<<dim3(8, 128, 1), blk, SMEM_SZ>>>(orr, wr + 0 * WSZ, b_q, q, EMB_, EMB_, EMB_, PROJ_, 1.0f, 1, 0, 0, 0);
    cudaEventRecord(eQ, 0);

    // ---- stream 1: sub rounds -> sk proj, vt proj -> (record eS)
    round_kernel<<<(NB4 + 255) / 256, 256, 0, st1>>>(sub, srr, NB4);
    round_kernel<<<(NW4 + 255) / 256, 256, 0, st1>>>(W_sk, wr + 1 * WSZ, NW4);
    round_kernel<<<(NW4 + 255) / 256, 256, 0, st1>>>(W_sv, wr + 2 * WSZ, NW4);
    mma_gemm<false><<<dim3(8, 64, 1), blk, SMEM_SZ, st1>>>(srr, wr + 1 * WSZ, b_sk, sk, EMB_, EMB_, EMB_, PROJ_, 1.0f, 1, 0, 0, 0);
    mma_gemm<true ><<<dim3(8, 64, 1), blk, SMEM_SZ, st1>>>(srr, wr + 2 * WSZ, b_sv, vt, EMB_, EMB_, EMB_, PROJ_, 1.0f, 1, 0, 0, 0);
    cudaEventRecord(eS, st1);

    // ---- stream 2: scene rounds -> ek proj, evt proj -> wait eQ -> attn2 chain
    round_kernel<<<(NB4 + 255) / 256, 256, 0, st2>>>(scene, crr, NB4);
    round_kernel<<<(NW4 + 255) / 256, 256, 0, st2>>>(W_ek, wr + 3 * WSZ, NW4);
    round_kernel<<<(NW4 + 255) / 256, 256, 0, st2>>>(W_ev, wr + 4 * WSZ, NW4);
    mma_gemm<false><<<dim3(8, 64, 1), blk, SMEM_SZ, st2>>>(crr, wr + 3 * WSZ, b_ek, ek, EMB_, EMB_, EMB_, PROJ_, 1.0f, 1, 0, 0, 0);
    mma_gemm<true ><<<dim3(8, 64, 1), blk, SMEM_SZ, st2>>>(crr, wr + 4 * WSZ, b_ev, evt, EMB_, EMB_, EMB_, PROJ_, 1.0f, 1, 0, 0, 0);
    cudaStreamWaitEvent(st2, eQ, 0);
    mma_gemm<false><<<dim3(8, 16, BB), blk, SMEM_SZ, st2>>>(q, ek, nullptr, S2, PROJ_, PROJ_, PROJ_, SKV, scale, 0, ZP, ZV, ZS);
    softmax_kernel<<<BB * SQ, dim3(256), 0, st2>>>(S2);
    mma_gemm<false><<<dim3(8, 16, BB), blk, SMEM_SZ, st2>>>(S2, evt, nullptr, O2, SKV, SKV, SKV, PROJ_, 1.0f, 0, ZS, ZV, ZP);
    ln_kernel<<<BB * SQ, dim3(256), 0, st2>>>(obj, O2, ln_g, ln_b);
    cudaEventRecord(eJoin, st2);

    // ---- stream 0: wait sub projections -> attn1 chain
    cudaStreamWaitEvent(0, eS, 0);
    mma_gemm<false><<<dim3(8, 16, BB), blk, SMEM_SZ>>>(q, sk, nullptr, S1, PROJ_, PROJ_, PROJ_, SKV, scale, 0, ZP, ZV, ZS);
    softmax_kernel<<<BB * SQ, dim3(256)>>>(S1);
    mma_gemm<false><<<dim3(8, 16, BB), blk, SMEM_SZ>>>(S1, vt, nullptr, O1, SKV, SKV, SKV, PROJ_, 1.0f, 0, ZS, ZV, ZP);
    ln_kernel<<<BB * SQ, dim3(256)>>>(obj, O1, ln_g, ln_b);

    // ---- join attn2 back into stream 0
    cudaStreamWaitEvent(0, eJoin, 0);
}